// round 13
// baseline (speedup 1.0000x reference)
#include <cuda_runtime.h>

#define NN   3072
#define H    8
#define DH   32
#define HIDD 256
#define DEG  16
#define EDIM 32
#define FFND 1024
#define EE   (NN*DEG)
#define RT   (NN/64)      // 48 row tiles

// ---------------- scratch (no allocations allowed) ----------------
__device__ float g_Q[NN*HIDD];
__device__ float g_K[NN*HIDD];
__device__ float g_V[NN*HIDD];
__device__ float g_attn[NN*HIDD];
__device__ float g_h1[NN*HIDD];
__device__ float g_h1t[NN*HIDD];
__device__ float g_ffn[NN*FFND];
__device__ float g_part[4*NN*HIDD];
__device__ float g_zero[HIDD];
__device__ unsigned g_ctr_wo[RT];     // zero-init; reset by fixup each launch
__device__ unsigned g_ctr_f2[RT];
// tf32-rounded operands
__device__ float g_xt[NN*HIDD];
__device__ float g_Wqt[HIDD*HIDD];
__device__ float g_Wkt[HIDD*HIDD];
__device__ float g_Wvt[HIDD*HIDD];
__device__ float g_Wot[HIDD*HIDD];
__device__ float g_Wf1t[HIDD*FFND];
__device__ float g_Wf2t[FFND*HIDD];

// ---------------- tf32 helpers ----------------
__device__ __forceinline__ float to_tf32(float x) {
    unsigned u;
    asm("cvt.rna.tf32.f32 %0, %1;" : "=r"(u) : "f"(x));
    return __uint_as_float(u);
}
__device__ __forceinline__ void mma_tf32(float* c, const unsigned* a, const unsigned* b) {
    asm volatile(
        "mma.sync.aligned.m16n8k8.row.col.f32.tf32.tf32.f32 "
        "{%0,%1,%2,%3},{%4,%5,%6,%7},{%8,%9},{%0,%1,%2,%3};"
        : "+f"(c[0]), "+f"(c[1]), "+f"(c[2]), "+f"(c[3])
        : "r"(a[0]), "r"(a[1]), "r"(a[2]), "r"(a[3]), "r"(b[0]), "r"(b[1]));
}
__device__ __forceinline__ void cpa16(unsigned s, const void* g) {
    asm volatile("cp.async.cg.shared.global [%0], [%1], 16;" :: "r"(s), "l"(g));
}

constexpr int LA = 36;
constexpr int LB = 72;
constexpr int ASZ = 64 * LA;
constexpr int BSZ = 32 * LB;
constexpr int GSMEM = 3 * (ASZ + BSZ) * (int)sizeof(float);   // 54 KB dynamic

// ---- pre-round all GEMM operands to tf32 (weights + x), 7 tensors --------
struct CvtArgs {
    const float* src[7];
    float*       dst[7];
    int          n4[7];
};
__global__ __launch_bounds__(256) void cvt_kernel(CvtArgs a) {
    const int id = blockIdx.y;
    const float4* s = (const float4*)a.src[id];
    float4*       d = (float4*)a.dst[id];
    const int n4 = a.n4[id];
    const int stride = gridDim.x * blockDim.x;
    for (int i = blockIdx.x * blockDim.x + threadIdx.x; i < n4; i += stride) {
        float4 v = s[i];
        d[i] = make_float4(to_tf32(v.x), to_tf32(v.y), to_tf32(v.z), to_tf32(v.w));
    }
}

// ---------------- tf32 GEMM body (pre-rounded operands, cvt-free loop) -----
template<bool RELU_RND>
__device__ __forceinline__ void gemm_body(
    const float* __restrict__ in, int lda,
    const float* __restrict__ W,
    const float* __restrict__ bias,
    float* __restrict__ out,
    int KTOT, int ldW, int r0, int cb0,
    float* As, float* Bs)
{
    const int tid  = threadIdx.x;
    const int warp = tid >> 5;
    const int lane = tid & 31;
    const int g    = lane >> 2;
    const int l    = lane & 3;
    const int wm   = warp & 3;
    const int wn   = warp >> 2;

    float c[4][4];
#pragma unroll
    for (int j = 0; j < 4; j++)
#pragma unroll
        for (int q = 0; q < 4; q++) c[j][q] = 0.f;

    const int am = tid >> 3, ac4 = tid & 7;
    const int bk = tid >> 4, bc4 = tid & 15;

    const unsigned uA = (unsigned)__cvta_generic_to_shared(As);
    const unsigned uB = (unsigned)__cvta_generic_to_shared(Bs);

    auto issue = [&](int ch) {
        const int st = ch % 3;
        const int kc = ch << 5;
        cpa16(uA + (unsigned)(st * ASZ + am * LA + ac4 * 4) * 4u,
              in + (size_t)(r0 + am) * lda + kc + ac4 * 4);
        cpa16(uA + (unsigned)(st * ASZ + (am + 32) * LA + ac4 * 4) * 4u,
              in + (size_t)(r0 + am + 32) * lda + kc + ac4 * 4);
        cpa16(uB + (unsigned)(st * BSZ + bk * LB + bc4 * 4) * 4u,
              W + (size_t)(kc + bk) * ldW + cb0 + bc4 * 4);
        cpa16(uB + (unsigned)(st * BSZ + (bk + 16) * LB + bc4 * 4) * 4u,
              W + (size_t)(kc + bk + 16) * ldW + cb0 + bc4 * 4);
        asm volatile("cp.async.commit_group;");
    };

    const int NC = KTOT >> 5;
    issue(0);
    if (NC > 1) issue(1);

    for (int ch = 0; ch < NC; ch++) {
        if (ch + 1 < NC) asm volatile("cp.async.wait_group 1;");
        else             asm volatile("cp.async.wait_group 0;");
        __syncthreads();
        if (ch + 2 < NC) issue(ch + 2);
        const float* Ac = As + (ch % 3) * ASZ;
        const float* Bc = Bs + (ch % 3) * BSZ;
#pragma unroll
        for (int ks = 0; ks < 4; ks++) {
            const int k0 = ks * 8;
            unsigned a[4];
            const int ar = wm * 16 + g;
            a[0] = __float_as_uint(Ac[ar * LA + k0 + l]);
            a[1] = __float_as_uint(Ac[(ar + 8) * LA + k0 + l]);
            a[2] = __float_as_uint(Ac[ar * LA + k0 + l + 4]);
            a[3] = __float_as_uint(Ac[(ar + 8) * LA + k0 + l + 4]);
#pragma unroll
            for (int j = 0; j < 4; j++) {
                unsigned b[2];
                const int bc = wn * 32 + j * 8 + g;
                b[0] = __float_as_uint(Bc[(k0 + l) * LB + bc]);
                b[1] = __float_as_uint(Bc[(k0 + l + 4) * LB + bc]);
                mma_tf32(c[j], a, b);
            }
        }
    }

    const int row0 = r0 + wm * 16 + g;
#pragma unroll
    for (int j = 0; j < 4; j++) {
        const int col = cb0 + wn * 32 + j * 8 + l * 2;
        const float b0 = bias[col], b1 = bias[col + 1];
        float v00 = c[j][0] + b0, v01 = c[j][1] + b1;
        float v10 = c[j][2] + b0, v11 = c[j][3] + b1;
        if (RELU_RND) {
            v00 = to_tf32(fmaxf(v00, 0.f)); v01 = to_tf32(fmaxf(v01, 0.f));
            v10 = to_tf32(fmaxf(v10, 0.f)); v11 = to_tf32(fmaxf(v11, 0.f));
        }
        *(float2*)&out[(size_t)row0 * ldW + col]       = make_float2(v00, v01);
        *(float2*)&out[(size_t)(row0 + 8) * ldW + col] = make_float2(v10, v11);
    }
}

// ---- inline split-K reduce + bias + residual + LN for one 64-row tile ----
// 256 threads: 8 warps x 8 rows each (warp-per-row style, looped).
template<int NPART, bool WRITE_T>
__device__ void ln_fix(
    const float* __restrict__ part,
    const float* __restrict__ bias2,
    const float* __restrict__ res,
    const float* __restrict__ lg, const float* __restrict__ lb,
    float* __restrict__ out, float* __restrict__ out_t, int row0)
{
    const int warp = threadIdx.x >> 5, lane = threadIdx.x & 31;
    const float4* b2p = (const float4*)bias2;
    const float4* gp  = (const float4*)lg;
    const float4* bp  = (const float4*)lb;
    const float4 c0 = b2p[lane], c1 = b2p[lane + 32];
    const float4 g0 = gp[lane],  g1 = gp[lane + 32];
    const float4 bb0 = bp[lane], bb1 = bp[lane + 32];

    for (int rr = 0; rr < 8; rr++) {
        const int row = row0 + warp * 8 + rr;
        const size_t off = (size_t)row * HIDD;
        const float4* rp = (const float4*)(res + off);

        float4 r0 = rp[lane], r1 = rp[lane + 32];
        float4 v0 = make_float4(r0.x + c0.x, r0.y + c0.y, r0.z + c0.z, r0.w + c0.w);
        float4 v1 = make_float4(r1.x + c1.x, r1.y + c1.y, r1.z + c1.z, r1.w + c1.w);
#pragma unroll
        for (int i = 0; i < NPART; i++) {
            const float4* pp = (const float4*)(part + (size_t)i * NN * HIDD + off);
            float4 a = pp[lane], b = pp[lane + 32];
            v0.x += a.x; v0.y += a.y; v0.z += a.z; v0.w += a.w;
            v1.x += b.x; v1.y += b.y; v1.z += b.z; v1.w += b.w;
        }

        float s  = v0.x + v0.y + v0.z + v0.w + v1.x + v1.y + v1.z + v1.w;
        float s2 = v0.x*v0.x + v0.y*v0.y + v0.z*v0.z + v0.w*v0.w
                 + v1.x*v1.x + v1.y*v1.y + v1.z*v1.z + v1.w*v1.w;
#pragma unroll
        for (int o = 16; o; o >>= 1) {
            s  += __shfl_xor_sync(0xffffffffu, s,  o);
            s2 += __shfl_xor_sync(0xffffffffu, s2, o);
        }
        const float mu = s * (1.f / 256.f);
        const float var = fmaxf(s2 * (1.f / 256.f) - mu * mu, 0.f);
        const float rs = rsqrtf(var + 1e-5f);

        float4 o0, o1;
        o0.x = (v0.x - mu) * rs * g0.x + bb0.x;  o0.y = (v0.y - mu) * rs * g0.y + bb0.y;
        o0.z = (v0.z - mu) * rs * g0.z + bb0.z;  o0.w = (v0.w - mu) * rs * g0.w + bb0.w;
        o1.x = (v1.x - mu) * rs * g1.x + bb1.x;  o1.y = (v1.y - mu) * rs * g1.y + bb1.y;
        o1.z = (v1.z - mu) * rs * g1.z + bb1.z;  o1.w = (v1.w - mu) * rs * g1.w + bb1.w;
        ((float4*)(out + off))[lane]      = o0;
        ((float4*)(out + off))[lane + 32] = o1;
        if (WRITE_T) {
            ((float4*)(out_t + off))[lane] =
                make_float4(to_tf32(o0.x), to_tf32(o0.y), to_tf32(o0.z), to_tf32(o0.w));
            ((float4*)(out_t + off))[lane + 32] =
                make_float4(to_tf32(o1.x), to_tf32(o1.y), to_tf32(o1.z), to_tf32(o1.w));
        }
    }
}

template<bool RELU_RND>
__global__ __launch_bounds__(256) void gemm_tc(
    const float* __restrict__ in, const float* __restrict__ W,
    const float* __restrict__ bias, float* __restrict__ out,
    int KTOT, int ldW)
{
    extern __shared__ float smem[];
    gemm_body<RELU_RND>(in, KTOT, W, bias, out, KTOT, ldW,
                        blockIdx.x * 64, blockIdx.y * 64, smem, smem + 3 * ASZ);
}

// fused QKV: blockIdx.y in [0,12)
__global__ __launch_bounds__(256) void gemm_qkv(
    const float* __restrict__ x,
    const float* __restrict__ Wq, const float* __restrict__ bq, float* __restrict__ oq,
    const float* __restrict__ Wk, const float* __restrict__ bk, float* __restrict__ ok,
    const float* __restrict__ Wv, const float* __restrict__ bv, float* __restrict__ ov)
{
    extern __shared__ float smem[];
    const int sel = blockIdx.y >> 2;
    const float* W = (sel == 0) ? Wq : (sel == 1) ? Wk : Wv;
    const float* b = (sel == 0) ? bq : (sel == 1) ? bk : bv;
    float*       o = (sel == 0) ? oq : (sel == 1) ? ok : ov;
    gemm_body<false>(x, HIDD, W, b, o, HIDD, HIDD,
                     blockIdx.x * 64, (blockIdx.y & 3) * 64, smem, smem + 3 * ASZ);
}

// Wo split-K=2 + fused LN1 fixup. grid (48, 4, 2); 8 blocks per row tile.
__global__ __launch_bounds__(256) void gemm_wo(
    const float* __restrict__ in, const float* __restrict__ Wo,
    const float* __restrict__ zero, float* __restrict__ part,
    const float* __restrict__ bo, const float* __restrict__ x,
    const float* __restrict__ ln1g, const float* __restrict__ ln1b,
    float* __restrict__ h1, float* __restrict__ h1t)
{
    extern __shared__ float smem[];
    const int z = blockIdx.z;
    gemm_body<false>(in + z * (HIDD / 2), HIDD,
                     Wo + (size_t)z * (HIDD / 2) * HIDD,
                     zero, part + (size_t)z * NN * HIDD, HIDD / 2, HIDD,
                     blockIdx.x * 64, blockIdx.y * 64, smem, smem + 3 * ASZ);
    __threadfence();
    __shared__ unsigned s_old;
    __syncthreads();
    if (threadIdx.x == 0) s_old = atomicAdd(&g_ctr_wo[blockIdx.x], 1u);
    __syncthreads();
    if (s_old == 8u - 1u) {
        ln_fix<2, true>(part, bo, x, ln1g, ln1b, h1, h1t, blockIdx.x * 64);
        __syncthreads();
        if (threadIdx.x == 0) g_ctr_wo[blockIdx.x] = 0u;
    }
}

// FFN-down split-K=4 + fused LN2 fixup. grid (48, 4, 4); 16 blocks per tile.
__global__ __launch_bounds__(256) void gemm_f2(
    const float* __restrict__ ffn, const float* __restrict__ Wf2,
    const float* __restrict__ zero, float* __restrict__ part,
    const float* __restrict__ bf2, const float* __restrict__ h1,
    const float* __restrict__ ln2g, const float* __restrict__ ln2b,
    float* __restrict__ out)
{
    extern __shared__ float smem[];
    const int z = blockIdx.z;
    gemm_body<false>(ffn + z * (FFND / 4), FFND,
                     Wf2 + (size_t)z * (FFND / 4) * HIDD,
                     zero, part + (size_t)z * NN * HIDD, FFND / 4, HIDD,
                     blockIdx.x * 64, blockIdx.y * 64, smem, smem + 3 * ASZ);
    __threadfence();
    __shared__ unsigned s_old;
    __syncthreads();
    if (threadIdx.x == 0) s_old = atomicAdd(&g_ctr_f2[blockIdx.x], 1u);
    __syncthreads();
    if (s_old == 16u - 1u) {
        ln_fix<4, false>(part, bf2, h1, ln2g, ln2b, out, nullptr, blockIdx.x * 64);
        __syncthreads();
        if (threadIdx.x == 0) g_ctr_f2[blockIdx.x] = 0u;
    }
}

// ---------------- attention: warp per (node, head), fused edge bias -------
__global__ __launch_bounds__(256) void attn2(
    const int*   __restrict__ neighbors,
    const float* __restrict__ ef,
    const float* __restrict__ We,
    const float* __restrict__ be,
    const float* __restrict__ Q,
    const float* __restrict__ K,
    const float* __restrict__ V,
    float* __restrict__ outp)
{
    const int n = blockIdx.x;
    const int h = threadIdx.x >> 5;
    const int lane = threadIdx.x & 31;
    const int tid = threadIdx.x;
    const unsigned FULL = 0xffffffffu;

    __shared__ float efs[DEG][33];
    __shared__ float Wes[256];
    __shared__ int s_nbr[DEG];
    __shared__ unsigned s_keep;

    {
        const float* eb = ef + (size_t)n * DEG * EDIM;
#pragma unroll
        for (int i = 0; i < 2; i++) {
            int lin = tid + i * 256;
            efs[lin >> 5][lin & 31] = eb[lin];
        }
        Wes[tid] = We[tid];
    }
    if (h == 0) {
        int v = (lane < DEG) ? neighbors[n * DEG + lane] : -1;
        bool keep = (lane < DEG);
#pragma unroll
        for (int d2 = 1; d2 < DEG; d2++) {
            int other = __shfl_sync(FULL, v, d2);
            if (d2 > lane && other == v) keep = false;
        }
        unsigned km = __ballot_sync(FULL, keep && lane < DEG);
        if (lane < DEG) s_nbr[lane] = v;
        if (lane == 0) s_keep = km;
    }
    __syncthreads();

    const int nb_l = (lane < DEG) ? s_nbr[lane] : 0;
    const unsigned km = s_keep;
    const float q = Q[(size_t)n * HIDD + h * DH + lane];

    float bias = be[h];
    if (lane < DEG) {
#pragma unroll
        for (int k = 0; k < EDIM; k++)
            bias = fmaf(efs[lane][k], Wes[k * 8 + h], bias);
    }

    float kv[DEG];
#pragma unroll
    for (int d = 0; d < DEG; d++) {
        int s = __shfl_sync(FULL, nb_l, d);
        kv[d] = K[(size_t)s * HIDD + h * DH + lane];
    }
    float myscore = -1e30f;
#pragma unroll
    for (int d = 0; d < DEG; d++) {
        float p = q * kv[d];
#pragma unroll
        for (int o = 16; o; o >>= 1) p += __shfl_xor_sync(FULL, p, o);
        if (lane == d) myscore = p;
    }

    const bool keep = (lane < DEG) && ((km >> lane) & 1u);
    myscore = keep ? fmaf(myscore, 0.17677669529663687f, bias) : -1e30f;

    float m = myscore;
#pragma unroll
    for (int o = 16; o; o >>= 1) m = fmaxf(m, __shfl_xor_sync(FULL, m, o));
    float e = keep ? expf(myscore - m) : 0.f;
    float ssum = e;
#pragma unroll
    for (int o = 16; o; o >>= 1) ssum += __shfl_xor_sync(FULL, ssum, o);
    const float w = e / ssum;

    float vv[DEG];
#pragma unroll
    for (int d = 0; d < DEG; d++) {
        int s = __shfl_sync(FULL, nb_l, d);
        vv[d] = V[(size_t)s * HIDD + h * DH + lane];
    }
    float acc = 0.f;
#pragma unroll
    for (int d = 0; d < DEG; d++) {
        float wd = __shfl_sync(FULL, w, d);
        acc = fmaf(wd, vv[d], acc);
    }
    outp[(size_t)n * HIDD + h * DH + lane] = to_tf32(acc);
}

// ---------------- launch ----------------
extern "C" void kernel_launch(void* const* d_in, const int* in_sizes, int n_in,
                              void* d_out, int out_size)
{
    const float* x    = (const float*)d_in[0];
    const int*   nb   = (const int*)  d_in[1];
    const float* ef   = (const float*)d_in[2];
    const float* Wq   = (const float*)d_in[3];
    const float* bq   = (const float*)d_in[4];
    const float* Wk   = (const float*)d_in[5];
    const float* bk   = (const float*)d_in[6];
    const float* Wv   = (const float*)d_in[7];
    const float* bv   = (const float*)d_in[8];
    const float* We   = (const float*)d_in[9];
    const float* be   = (const float*)d_in[10];
    const float* Wo   = (const float*)d_in[11];
    const float* bo   = (const float*)d_in[12];
    const float* ln1g = (const float*)d_in[13];
    const float* ln1b = (const float*)d_in[14];
    const float* ln2g = (const float*)d_in[15];
    const float* ln2b = (const float*)d_in[16];
    const float* Wf1  = (const float*)d_in[17];
    const float* bf1  = (const float*)d_in[18];
    const float* Wf2  = (const float*)d_in[19];
    const float* bf2  = (const float*)d_in[20];
    float* out = (float*)d_out;

    float *pQ, *pK, *pV, *pA, *pH1, *pH1t, *pF, *pP, *pZ;
    float *pXt, *pWqt, *pWkt, *pWvt, *pWot, *pWf1t, *pWf2t;
    cudaGetSymbolAddress((void**)&pQ,   g_Q);
    cudaGetSymbolAddress((void**)&pK,   g_K);
    cudaGetSymbolAddress((void**)&pV,   g_V);
    cudaGetSymbolAddress((void**)&pA,   g_attn);
    cudaGetSymbolAddress((void**)&pH1,  g_h1);
    cudaGetSymbolAddress((void**)&pH1t, g_h1t);
    cudaGetSymbolAddress((void**)&pF,   g_ffn);
    cudaGetSymbolAddress((void**)&pP,   g_part);
    cudaGetSymbolAddress((void**)&pZ,   g_zero);
    cudaGetSymbolAddress((void**)&pXt,  g_xt);
    cudaGetSymbolAddress((void**)&pWqt, g_Wqt);
    cudaGetSymbolAddress((void**)&pWkt, g_Wkt);
    cudaGetSymbolAddress((void**)&pWvt, g_Wvt);
    cudaGetSymbolAddress((void**)&pWot, g_Wot);
    cudaGetSymbolAddress((void**)&pWf1t, g_Wf1t);
    cudaGetSymbolAddress((void**)&pWf2t, g_Wf2t);

    cudaFuncSetAttribute(gemm_qkv,      cudaFuncAttributeMaxDynamicSharedMemorySize, GSMEM);
    cudaFuncSetAttribute(gemm_wo,       cudaFuncAttributeMaxDynamicSharedMemorySize, GSMEM);
    cudaFuncSetAttribute(gemm_f2,       cudaFuncAttributeMaxDynamicSharedMemorySize, GSMEM);
    cudaFuncSetAttribute(gemm_tc<true>, cudaFuncAttributeMaxDynamicSharedMemorySize, GSMEM);

    // pre-round all GEMM operands to tf32
    CvtArgs ca;
    ca.src[0] = x;   ca.dst[0] = pXt;   ca.n4[0] = NN * HIDD / 4;
    ca.src[1] = Wq;  ca.dst[1] = pWqt;  ca.n4[1] = HIDD * HIDD / 4;
    ca.src[2] = Wk;  ca.dst[2] = pWkt;  ca.n4[2] = HIDD * HIDD / 4;
    ca.src[3] = Wv;  ca.dst[3] = pWvt;  ca.n4[3] = HIDD * HIDD / 4;
    ca.src[4] = Wo;  ca.dst[4] = pWot;  ca.n4[4] = HIDD * HIDD / 4;
    ca.src[5] = Wf1; ca.dst[5] = pWf1t; ca.n4[5] = HIDD * FFND / 4;
    ca.src[6] = Wf2; ca.dst[6] = pWf2t; ca.n4[6] = FFND * HIDD / 4;
    cvt_kernel<<<dim3(64, 7), 256>>>(ca);

    // fused QKV projection
    gemm_qkv<<<dim3(NN / 64, 12), 256, GSMEM>>>(pXt, pWqt, bq, pQ, pWkt, bk, pK, pWvt, bv, pV);

    // sparse attention with fused edge-bias projection (output tf32-rounded)
    attn2<<<NN, 256>>>(nb, ef, We, be, pQ, pK, pV, pA);

    // Wo split-K=2 with inline LN1 fixup -> h1, h1t
    gemm_wo<<<dim3(NN / 64, HIDD / 64, 2), 256, GSMEM>>>(
        pA, pWot, pZ, pP, bo, x, ln1g, ln1b, pH1, pH1t);

    // FFN up + ReLU (output tf32-rounded)
    gemm_tc<true><<<dim3(NN / 64, FFND / 64), 256, GSMEM>>>(pH1t, pWf1t, bf1, pF, HIDD, FFND);

    // FFN down split-K=4 with inline LN2 fixup -> out
    gemm_f2<<<dim3(NN / 64, HIDD / 64, 4), 256, GSMEM>>>(
        pF, pWf2t, pZ, pP, bf2, pH1, ln2g, ln2b, out);
}

// round 15
// speedup vs baseline: 1.1851x; 1.1851x over previous
#include <cuda_runtime.h>

#define NN   3072
#define H    8
#define DH   32
#define HIDD 256
#define DEG  16
#define EDIM 32
#define FFND 1024
#define EE   (NN*DEG)

// ---------------- scratch (no allocations allowed) ----------------
__device__ float g_Q[NN*HIDD];
__device__ float g_K[NN*HIDD];
__device__ float g_V[NN*HIDD];
__device__ float g_attn[NN*HIDD];
__device__ float g_h1[NN*HIDD];       // tf32-rounded h1 (f1 A operand + LN2 residual)
__device__ float g_ffn[NN*FFND];
__device__ float g_part[4*NN*HIDD];   // split-K partials (contiguous)
__device__ float g_zero[HIDD];        // zero bias (device globals are zeroed)
// tf32-rounded weights for later GEMMs (filled by qkv's extra blocks)
__device__ float g_Wot[HIDD*HIDD];
__device__ float g_Wf1t[HIDD*FFND];
__device__ float g_Wf2t[FFND*HIDD];

// ---------------- tf32 helpers ----------------
__device__ __forceinline__ float to_tf32(float x) {
    unsigned u;
    asm("cvt.rna.tf32.f32 %0, %1;" : "=r"(u) : "f"(x));
    return __uint_as_float(u);
}
__device__ __forceinline__ unsigned tf32_bits(float x) {
    unsigned u;
    asm("cvt.rna.tf32.f32 %0, %1;" : "=r"(u) : "f"(x));
    return u;
}
__device__ __forceinline__ void mma_tf32(float* c, const unsigned* a, const unsigned* b) {
    asm volatile(
        "mma.sync.aligned.m16n8k8.row.col.f32.tf32.tf32.f32 "
        "{%0,%1,%2,%3},{%4,%5,%6,%7},{%8,%9},{%0,%1,%2,%3};"
        : "+f"(c[0]), "+f"(c[1]), "+f"(c[2]), "+f"(c[3])
        : "r"(a[0]), "r"(a[1]), "r"(a[2]), "r"(a[3]), "r"(b[0]), "r"(b[1]));
}
__device__ __forceinline__ void cpa16(unsigned s, const void* g) {
    asm volatile("cp.async.cg.shared.global [%0], [%1], 16;" :: "r"(s), "l"(g));
}

constexpr int LA = 36;   // A smem pitch -> conflict-free frag LDS
constexpr int LB = 72;   // B smem pitch -> conflict-free frag LDS
constexpr int ASZ = 64 * LA;
constexpr int BSZ = 32 * LB;
constexpr int GSMEM = 3 * (ASZ + BSZ) * (int)sizeof(float);   // 54 KB dynamic

// ---------------- tf32 GEMM body: 64x64 tile, 256 threads ------------------
// cp.async 3-stage pipeline. CVT: round fragments at load (raw operands);
// otherwise operands are pre-rounded and the loop is cvt-free.
template<bool RELU_RND, bool CVT>
__device__ __forceinline__ void gemm_body(
    const float* __restrict__ in, int lda,
    const float* __restrict__ W,
    const float* __restrict__ bias,
    float* __restrict__ out,
    int KTOT, int ldW, int r0, int cb0,
    float* As, float* Bs)
{
    const int tid  = threadIdx.x;
    const int warp = tid >> 5;
    const int lane = tid & 31;
    const int g    = lane >> 2;
    const int l    = lane & 3;
    const int wm   = warp & 3;
    const int wn   = warp >> 2;

    float c[4][4];
#pragma unroll
    for (int j = 0; j < 4; j++)
#pragma unroll
        for (int q = 0; q < 4; q++) c[j][q] = 0.f;

    const int am = tid >> 3, ac4 = tid & 7;
    const int bk = tid >> 4, bc4 = tid & 15;

    const unsigned uA = (unsigned)__cvta_generic_to_shared(As);
    const unsigned uB = (unsigned)__cvta_generic_to_shared(Bs);

    auto issue = [&](int ch) {
        const int st = ch % 3;
        const int kc = ch << 5;
        cpa16(uA + (unsigned)(st * ASZ + am * LA + ac4 * 4) * 4u,
              in + (size_t)(r0 + am) * lda + kc + ac4 * 4);
        cpa16(uA + (unsigned)(st * ASZ + (am + 32) * LA + ac4 * 4) * 4u,
              in + (size_t)(r0 + am + 32) * lda + kc + ac4 * 4);
        cpa16(uB + (unsigned)(st * BSZ + bk * LB + bc4 * 4) * 4u,
              W + (size_t)(kc + bk) * ldW + cb0 + bc4 * 4);
        cpa16(uB + (unsigned)(st * BSZ + (bk + 16) * LB + bc4 * 4) * 4u,
              W + (size_t)(kc + bk + 16) * ldW + cb0 + bc4 * 4);
        asm volatile("cp.async.commit_group;");
    };

    const int NC = KTOT >> 5;
    issue(0);
    if (NC > 1) issue(1);

    for (int ch = 0; ch < NC; ch++) {
        if (ch + 1 < NC) asm volatile("cp.async.wait_group 1;");
        else             asm volatile("cp.async.wait_group 0;");
        __syncthreads();
        if (ch + 2 < NC) issue(ch + 2);
        const float* Ac = As + (ch % 3) * ASZ;
        const float* Bc = Bs + (ch % 3) * BSZ;
#pragma unroll
        for (int ks = 0; ks < 4; ks++) {
            const int k0 = ks * 8;
            unsigned a[4];
            const int ar = wm * 16 + g;
            if (CVT) {
                a[0] = tf32_bits(Ac[ar * LA + k0 + l]);
                a[1] = tf32_bits(Ac[(ar + 8) * LA + k0 + l]);
                a[2] = tf32_bits(Ac[ar * LA + k0 + l + 4]);
                a[3] = tf32_bits(Ac[(ar + 8) * LA + k0 + l + 4]);
            } else {
                a[0] = __float_as_uint(Ac[ar * LA + k0 + l]);
                a[1] = __float_as_uint(Ac[(ar + 8) * LA + k0 + l]);
                a[2] = __float_as_uint(Ac[ar * LA + k0 + l + 4]);
                a[3] = __float_as_uint(Ac[(ar + 8) * LA + k0 + l + 4]);
            }
#pragma unroll
            for (int j = 0; j < 4; j++) {
                unsigned b[2];
                const int bc = wn * 32 + j * 8 + g;
                if (CVT) {
                    b[0] = tf32_bits(Bc[(k0 + l) * LB + bc]);
                    b[1] = tf32_bits(Bc[(k0 + l + 4) * LB + bc]);
                } else {
                    b[0] = __float_as_uint(Bc[(k0 + l) * LB + bc]);
                    b[1] = __float_as_uint(Bc[(k0 + l + 4) * LB + bc]);
                }
                mma_tf32(c[j], a, b);
            }
        }
    }

    const int row0 = r0 + wm * 16 + g;
#pragma unroll
    for (int j = 0; j < 4; j++) {
        const int col = cb0 + wn * 32 + j * 8 + l * 2;
        const float b0 = bias[col], b1 = bias[col + 1];
        float v00 = c[j][0] + b0, v01 = c[j][1] + b1;
        float v10 = c[j][2] + b0, v11 = c[j][3] + b1;
        if (RELU_RND) {   // f1: relu then round (feeds f2's cvt-free A)
            v00 = to_tf32(fmaxf(v00, 0.f)); v01 = to_tf32(fmaxf(v01, 0.f));
            v10 = to_tf32(fmaxf(v10, 0.f)); v11 = to_tf32(fmaxf(v11, 0.f));
        }
        *(float2*)&out[(size_t)row0 * ldW + col]       = make_float2(v00, v01);
        *(float2*)&out[(size_t)(row0 + 8) * ldW + col] = make_float2(v10, v11);
    }
}

template<bool RELU_RND>
__global__ __launch_bounds__(256) void gemm_tc(
    const float* __restrict__ in, const float* __restrict__ W,
    const float* __restrict__ bias, float* __restrict__ out,
    int KTOT, int ldW)
{
    extern __shared__ float smem[];
    gemm_body<RELU_RND, false>(in, KTOT, W, bias, out, KTOT, ldW,
                               blockIdx.x * 64, blockIdx.y * 64, smem, smem + 3 * ASZ);
}

// fused QKV (raw operands, in-loop cvt) + piggybacked weight rounding:
// blockIdx.y in [0,12) -> GEMM; [12,14) -> round Wo/Wf1/Wf2 for later kernels.
__global__ __launch_bounds__(256) void gemm_qkv(
    const float* __restrict__ x,
    const float* __restrict__ Wq, const float* __restrict__ bq, float* __restrict__ oq,
    const float* __restrict__ Wk, const float* __restrict__ bk, float* __restrict__ ok,
    const float* __restrict__ Wv, const float* __restrict__ bv, float* __restrict__ ov,
    const float* __restrict__ Wo,  float* __restrict__ dWo,
    const float* __restrict__ Wf1, float* __restrict__ dWf1,
    const float* __restrict__ Wf2, float* __restrict__ dWf2)
{
    extern __shared__ float smem[];
    if (blockIdx.y >= 12) {
        constexpr int n1 = HIDD * HIDD / 4;
        constexpr int n2 = HIDD * FFND / 4;
        constexpr int n3 = FFND * HIDD / 4;
        const int base = ((blockIdx.y - 12) * gridDim.x + blockIdx.x) * blockDim.x + threadIdx.x;
        const int step = 2 * gridDim.x * blockDim.x;
        for (int i = base; i < n1 + n2 + n3; i += step) {
            const float4* s; float4* d; int j = i;
            if (j < n1)           { s = (const float4*)Wo;  d = (float4*)dWo; }
            else if (j < n1 + n2) { j -= n1; s = (const float4*)Wf1; d = (float4*)dWf1; }
            else                  { j -= n1 + n2; s = (const float4*)Wf2; d = (float4*)dWf2; }
            float4 v = s[j];
            d[j] = make_float4(to_tf32(v.x), to_tf32(v.y), to_tf32(v.z), to_tf32(v.w));
        }
        return;
    }
    const int sel = blockIdx.y >> 2;
    const float* W = (sel == 0) ? Wq : (sel == 1) ? Wk : Wv;
    const float* b = (sel == 0) ? bq : (sel == 1) ? bk : bv;
    float*       o = (sel == 0) ? oq : (sel == 1) ? ok : ov;
    gemm_body<false, true>(x, HIDD, W, b, o, HIDD, HIDD,
                           blockIdx.x * 64, (blockIdx.y & 3) * 64, smem, smem + 3 * ASZ);
}

// Wo, split-K=2: grid (48, 4, 2). K=128 per split; operands pre-rounded.
__global__ __launch_bounds__(256) void gemm_wo(
    const float* __restrict__ in, const float* __restrict__ Wo,
    const float* __restrict__ zero, float* __restrict__ part)
{
    extern __shared__ float smem[];
    const int z = blockIdx.z;
    gemm_body<false, false>(in + z * (HIDD / 2), HIDD,
                            Wo + (size_t)z * (HIDD / 2) * HIDD,
                            zero, part + (size_t)z * NN * HIDD, HIDD / 2, HIDD,
                            blockIdx.x * 64, blockIdx.y * 64, smem, smem + 3 * ASZ);
}

// FFN-down, split-K=4: grid (48, 4, 4). K=256 per split; pre-rounded.
__global__ __launch_bounds__(256) void gemm_f2(
    const float* __restrict__ ffn, const float* __restrict__ Wf2,
    const float* __restrict__ zero, float* __restrict__ part)
{
    extern __shared__ float smem[];
    const int z = blockIdx.z;
    gemm_body<false, false>(ffn + z * (FFND / 4), FFND,
                            Wf2 + (size_t)z * (FFND / 4) * HIDD,
                            zero, part + (size_t)z * NN * HIDD, FFND / 4, HIDD,
                            blockIdx.x * 64, blockIdx.y * 64, smem, smem + 3 * ASZ);
}

// ---------------- attention: warp per (node, head), fused edge bias -------
// output rounded to tf32 (feeds Wo's cvt-free A operand)
__global__ __launch_bounds__(256) void attn2(
    const int*   __restrict__ neighbors,
    const float* __restrict__ ef,
    const float* __restrict__ We,
    const float* __restrict__ be,
    const float* __restrict__ Q,
    const float* __restrict__ K,
    const float* __restrict__ V,
    float* __restrict__ outp)
{
    const int n = blockIdx.x;
    const int h = threadIdx.x >> 5;
    const int lane = threadIdx.x & 31;
    const int tid = threadIdx.x;
    const unsigned FULL = 0xffffffffu;

    __shared__ float efs[DEG][33];
    __shared__ float Wes[256];
    __shared__ int s_nbr[DEG];
    __shared__ unsigned s_keep;

    {
        const float* eb = ef + (size_t)n * DEG * EDIM;
#pragma unroll
        for (int i = 0; i < 2; i++) {
            int lin = tid + i * 256;
            efs[lin >> 5][lin & 31] = eb[lin];
        }
        Wes[tid] = We[tid];
    }
    if (h == 0) {
        int v = (lane < DEG) ? neighbors[n * DEG + lane] : -1;
        bool keep = (lane < DEG);
#pragma unroll
        for (int d2 = 1; d2 < DEG; d2++) {
            int other = __shfl_sync(FULL, v, d2);
            if (d2 > lane && other == v) keep = false;
        }
        unsigned km = __ballot_sync(FULL, keep && lane < DEG);
        if (lane < DEG) s_nbr[lane] = v;
        if (lane == 0) s_keep = km;
    }
    __syncthreads();

    const int nb_l = (lane < DEG) ? s_nbr[lane] : 0;
    const unsigned km = s_keep;
    const float q = Q[(size_t)n * HIDD + h * DH + lane];

    float bias = be[h];
    if (lane < DEG) {
#pragma unroll
        for (int k = 0; k < EDIM; k++)
            bias = fmaf(efs[lane][k], Wes[k * 8 + h], bias);
    }

    float kv[DEG];
#pragma unroll
    for (int d = 0; d < DEG; d++) {
        int s = __shfl_sync(FULL, nb_l, d);
        kv[d] = K[(size_t)s * HIDD + h * DH + lane];
    }
    float myscore = -1e30f;
#pragma unroll
    for (int d = 0; d < DEG; d++) {
        float p = q * kv[d];
#pragma unroll
        for (int o = 16; o; o >>= 1) p += __shfl_xor_sync(FULL, p, o);
        if (lane == d) myscore = p;
    }

    const bool keep = (lane < DEG) && ((km >> lane) & 1u);
    myscore = keep ? fmaf(myscore, 0.17677669529663687f, bias) : -1e30f;

    float m = myscore;
#pragma unroll
    for (int o = 16; o; o >>= 1) m = fmaxf(m, __shfl_xor_sync(FULL, m, o));
    float e = keep ? expf(myscore - m) : 0.f;
    float ssum = e;
#pragma unroll
    for (int o = 16; o; o >>= 1) ssum += __shfl_xor_sync(FULL, ssum, o);
    const float w = e / ssum;

    float vv[DEG];
#pragma unroll
    for (int d = 0; d < DEG; d++) {
        int s = __shfl_sync(FULL, nb_l, d);
        vv[d] = V[(size_t)s * HIDD + h * DH + lane];
    }
    float acc = 0.f;
#pragma unroll
    for (int d = 0; d < DEG; d++) {
        float wd = __shfl_sync(FULL, w, d);
        acc = fmaf(wd, vv[d], acc);
    }
    outp[(size_t)n * HIDD + h * DH + lane] = to_tf32(acc);
}

// ---- N-partial reduce + bias + residual + LayerNorm (warp per row) -------
// RND: round the stored output to tf32 (h1 path: feeds f1's A and LN2 res).
template<int NPART, bool RND>
__global__ __launch_bounds__(256) void ln_red(
    const float* __restrict__ part,
    const float* __restrict__ bias2,
    const float* __restrict__ res,
    const float* __restrict__ lg, const float* __restrict__ lb,
    float* __restrict__ out)
{
    const int warp = threadIdx.x >> 5, lane = threadIdx.x & 31;
    const int row = blockIdx.x * 8 + warp;
    const size_t off = (size_t)row * HIDD;
    const float4* rp  = (const float4*)(res + off);
    const float4* b2p = (const float4*)bias2;

    float4 v0, v1;
    {
        float4 r = rp[lane], c = b2p[lane];
        v0 = make_float4(r.x + c.x, r.y + c.y, r.z + c.z, r.w + c.w);
    }
    {
        float4 r = rp[lane + 32], c = b2p[lane + 32];
        v1 = make_float4(r.x + c.x, r.y + c.y, r.z + c.z, r.w + c.w);
    }
#pragma unroll
    for (int i = 0; i < NPART; i++) {
        const float4* pp = (const float4*)(part + (size_t)i * NN * HIDD + off);
        float4 a = pp[lane], b = pp[lane + 32];
        v0.x += a.x; v0.y += a.y; v0.z += a.z; v0.w += a.w;
        v1.x += b.x; v1.y += b.y; v1.z += b.z; v1.w += b.w;
    }

    float s  = v0.x + v0.y + v0.z + v0.w + v1.x + v1.y + v1.z + v1.w;
    float s2 = v0.x*v0.x + v0.y*v0.y + v0.z*v0.z + v0.w*v0.w
             + v1.x*v1.x + v1.y*v1.y + v1.z*v1.z + v1.w*v1.w;
#pragma unroll
    for (int o = 16; o; o >>= 1) {
        s  += __shfl_xor_sync(0xffffffffu, s,  o);
        s2 += __shfl_xor_sync(0xffffffffu, s2, o);
    }
    const float mu = s * (1.f / 256.f);
    const float var = fmaxf(s2 * (1.f / 256.f) - mu * mu, 0.f);
    const float rs = rsqrtf(var + 1e-5f);

    const float4* gp = (const float4*)lg;
    const float4* bp = (const float4*)lb;
    float4 g0 = gp[lane], g1 = gp[lane + 32];
    float4 b0 = bp[lane], b1 = bp[lane + 32];
    float4 o0, o1;
    o0.x = (v0.x - mu) * rs * g0.x + b0.x;  o0.y = (v0.y - mu) * rs * g0.y + b0.y;
    o0.z = (v0.z - mu) * rs * g0.z + b0.z;  o0.w = (v0.w - mu) * rs * g0.w + b0.w;
    o1.x = (v1.x - mu) * rs * g1.x + b1.x;  o1.y = (v1.y - mu) * rs * g1.y + b1.y;
    o1.z = (v1.z - mu) * rs * g1.z + b1.z;  o1.w = (v1.w - mu) * rs * g1.w + b1.w;
    if (RND) {
        o0 = make_float4(to_tf32(o0.x), to_tf32(o0.y), to_tf32(o0.z), to_tf32(o0.w));
        o1 = make_float4(to_tf32(o1.x), to_tf32(o1.y), to_tf32(o1.z), to_tf32(o1.w));
    }
    ((float4*)(out + off))[lane]      = o0;
    ((float4*)(out + off))[lane + 32] = o1;
}

// ---------------- launch ----------------
extern "C" void kernel_launch(void* const* d_in, const int* in_sizes, int n_in,
                              void* d_out, int out_size)
{
    const float* x    = (const float*)d_in[0];
    const int*   nb   = (const int*)  d_in[1];
    const float* ef   = (const float*)d_in[2];
    const float* Wq   = (const float*)d_in[3];
    const float* bq   = (const float*)d_in[4];
    const float* Wk   = (const float*)d_in[5];
    const float* bk   = (const float*)d_in[6];
    const float* Wv   = (const float*)d_in[7];
    const float* bv   = (const float*)d_in[8];
    const float* We   = (const float*)d_in[9];
    const float* be   = (const float*)d_in[10];
    const float* Wo   = (const float*)d_in[11];
    const float* bo   = (const float*)d_in[12];
    const float* ln1g = (const float*)d_in[13];
    const float* ln1b = (const float*)d_in[14];
    const float* ln2g = (const float*)d_in[15];
    const float* ln2b = (const float*)d_in[16];
    const float* Wf1  = (const float*)d_in[17];
    const float* bf1  = (const float*)d_in[18];
    const float* Wf2  = (const float*)d_in[19];
    const float* bf2  = (const float*)d_in[20];
    float* out = (float*)d_out;

    float *pQ, *pK, *pV, *pA, *pH1, *pF, *pP, *pZ;
    float *pWot, *pWf1t, *pWf2t;
    cudaGetSymbolAddress((void**)&pQ,   g_Q);
    cudaGetSymbolAddress((void**)&pK,   g_K);
    cudaGetSymbolAddress((void**)&pV,   g_V);
    cudaGetSymbolAddress((void**)&pA,   g_attn);
    cudaGetSymbolAddress((void**)&pH1,  g_h1);
    cudaGetSymbolAddress((void**)&pF,   g_ffn);
    cudaGetSymbolAddress((void**)&pP,   g_part);
    cudaGetSymbolAddress((void**)&pZ,   g_zero);
    cudaGetSymbolAddress((void**)&pWot, g_Wot);
    cudaGetSymbolAddress((void**)&pWf1t, g_Wf1t);
    cudaGetSymbolAddress((void**)&pWf2t, g_Wf2t);

    cudaFuncSetAttribute(gemm_qkv,      cudaFuncAttributeMaxDynamicSharedMemorySize, GSMEM);
    cudaFuncSetAttribute(gemm_wo,       cudaFuncAttributeMaxDynamicSharedMemorySize, GSMEM);
    cudaFuncSetAttribute(gemm_f2,       cudaFuncAttributeMaxDynamicSharedMemorySize, GSMEM);
    cudaFuncSetAttribute(gemm_tc<true>, cudaFuncAttributeMaxDynamicSharedMemorySize, GSMEM);

    // fused QKV (in-loop cvt) + piggybacked rounding of Wo/Wf1/Wf2
    gemm_qkv<<<dim3(NN / 64, 14), 256, GSMEM>>>(
        x, Wq, bq, pQ, Wk, bk, pK, Wv, bv, pV,
        Wo, pWot, Wf1, pWf1t, Wf2, pWf2t);

    // sparse attention with fused edge-bias projection (output tf32-rounded)
    attn2<<<NN, 256>>>(nb, ef, We, be, pQ, pK, pV, pA);

    // Wo split-K=2 -> 2 partials; reduce + bo + residual(x) + LN1 -> h1 (rounded)
    gemm_wo<<<dim3(NN / 64, HIDD / 64, 2), 256, GSMEM>>>(pA, pWot, pZ, pP);
    ln_red<2, true><<<NN / 8, 256>>>(pP, bo, x, ln1g, ln1b, pH1);

    // FFN up + ReLU (output tf32-rounded in epilogue)
    gemm_tc<true><<<dim3(NN / 64, FFND / 64), 256, GSMEM>>>(pH1, pWf1t, bf1, pF, HIDD, FFND);

    // FFN down split-K=4 -> 4 partials; reduce + bf2 + res(h1) + LN2 -> out
    gemm_f2<<<dim3(NN / 64, HIDD / 64, 4), 256, GSMEM>>>(pF, pWf2t, pZ, pP);
    ln_red<4, false><<<NN / 8, 256>>>(pP, bf2, pH1, ln2g, ln2b, out);
}

// round 16
// speedup vs baseline: 1.2411x; 1.0473x over previous
#include <cuda_runtime.h>

#define NN   3072
#define H    8
#define DH   32
#define HIDD 256
#define DEG  16
#define EDIM 32
#define FFND 1024
#define EE   (NN*DEG)

// ---------------- scratch (no allocations allowed) ----------------
__device__ float g_Q[NN*HIDD];
__device__ float g_K[NN*HIDD];
__device__ float g_V[NN*HIDD];
__device__ float g_attn[NN*HIDD];
__device__ float g_h1[NN*HIDD];       // tf32-rounded h1 (f1 A operand + LN2 residual)
__device__ float g_ffn[NN*FFND];
__device__ float g_part[4*NN*HIDD];   // split-K partials (contiguous)
__device__ float g_zero[HIDD];        // zero bias (device globals are zeroed)
// tf32-rounded weights for later GEMMs (filled by qkv's extra blocks)
__device__ float g_Wot[HIDD*HIDD];
__device__ float g_Wf1t[HIDD*FFND];
__device__ float g_Wf2t[FFND*HIDD];

// ---------------- PDL helpers ----------------
__device__ __forceinline__ void gdc_wait() {
    asm volatile("griddepcontrol.wait;" ::: "memory");
}
__device__ __forceinline__ void gdc_launch() {
    asm volatile("griddepcontrol.launch_dependents;");
}

// ---------------- tf32 helpers ----------------
__device__ __forceinline__ float to_tf32(float x) {
    unsigned u;
    asm("cvt.rna.tf32.f32 %0, %1;" : "=r"(u) : "f"(x));
    return __uint_as_float(u);
}
__device__ __forceinline__ unsigned tf32_bits(float x) {
    unsigned u;
    asm("cvt.rna.tf32.f32 %0, %1;" : "=r"(u) : "f"(x));
    return u;
}
__device__ __forceinline__ void mma_tf32(float* c, const unsigned* a, const unsigned* b) {
    asm volatile(
        "mma.sync.aligned.m16n8k8.row.col.f32.tf32.tf32.f32 "
        "{%0,%1,%2,%3},{%4,%5,%6,%7},{%8,%9},{%0,%1,%2,%3};"
        : "+f"(c[0]), "+f"(c[1]), "+f"(c[2]), "+f"(c[3])
        : "r"(a[0]), "r"(a[1]), "r"(a[2]), "r"(a[3]), "r"(b[0]), "r"(b[1]));
}
__device__ __forceinline__ void cpa16(unsigned s, const void* g) {
    asm volatile("cp.async.cg.shared.global [%0], [%1], 16;" :: "r"(s), "l"(g));
}

constexpr int LA = 36;   // A smem pitch -> conflict-free frag LDS
constexpr int LB = 72;   // B smem pitch -> conflict-free frag LDS
constexpr int ASZ = 64 * LA;
constexpr int BSZ = 32 * LB;
constexpr int GSMEM = 3 * (ASZ + BSZ) * (int)sizeof(float);   // 54 KB dynamic

// ---------------- tf32 GEMM body: 64x64 tile, 256 threads ------------------
// cp.async 3-stage pipeline. CVT: round fragments at load (raw operands);
// otherwise operands are pre-rounded and the loop is cvt-free.
template<bool RELU_RND, bool CVT>
__device__ __forceinline__ void gemm_body(
    const float* __restrict__ in, int lda,
    const float* __restrict__ W,
    const float* __restrict__ bias,
    float* __restrict__ out,
    int KTOT, int ldW, int r0, int cb0,
    float* As, float* Bs)
{
    const int tid  = threadIdx.x;
    const int warp = tid >> 5;
    const int lane = tid & 31;
    const int g    = lane >> 2;
    const int l    = lane & 3;
    const int wm   = warp & 3;
    const int wn   = warp >> 2;

    float c[4][4];
#pragma unroll
    for (int j = 0; j < 4; j++)
#pragma unroll
        for (int q = 0; q < 4; q++) c[j][q] = 0.f;

    const int am = tid >> 3, ac4 = tid & 7;
    const int bk = tid >> 4, bc4 = tid & 15;

    const unsigned uA = (unsigned)__cvta_generic_to_shared(As);
    const unsigned uB = (unsigned)__cvta_generic_to_shared(Bs);

    auto issue = [&](int ch) {
        const int st = ch % 3;
        const int kc = ch << 5;
        cpa16(uA + (unsigned)(st * ASZ + am * LA + ac4 * 4) * 4u,
              in + (size_t)(r0 + am) * lda + kc + ac4 * 4);
        cpa16(uA + (unsigned)(st * ASZ + (am + 32) * LA + ac4 * 4) * 4u,
              in + (size_t)(r0 + am + 32) * lda + kc + ac4 * 4);
        cpa16(uB + (unsigned)(st * BSZ + bk * LB + bc4 * 4) * 4u,
              W + (size_t)(kc + bk) * ldW + cb0 + bc4 * 4);
        cpa16(uB + (unsigned)(st * BSZ + (bk + 16) * LB + bc4 * 4) * 4u,
              W + (size_t)(kc + bk + 16) * ldW + cb0 + bc4 * 4);
        asm volatile("cp.async.commit_group;");
    };

    const int NC = KTOT >> 5;
    issue(0);
    if (NC > 1) issue(1);

    for (int ch = 0; ch < NC; ch++) {
        if (ch + 1 < NC) asm volatile("cp.async.wait_group 1;");
        else             asm volatile("cp.async.wait_group 0;");
        __syncthreads();
        if (ch + 2 < NC) issue(ch + 2);
        const float* Ac = As + (ch % 3) * ASZ;
        const float* Bc = Bs + (ch % 3) * BSZ;
#pragma unroll
        for (int ks = 0; ks < 4; ks++) {
            const int k0 = ks * 8;
            unsigned a[4];
            const int ar = wm * 16 + g;
            if (CVT) {
                a[0] = tf32_bits(Ac[ar * LA + k0 + l]);
                a[1] = tf32_bits(Ac[(ar + 8) * LA + k0 + l]);
                a[2] = tf32_bits(Ac[ar * LA + k0 + l + 4]);
                a[3] = tf32_bits(Ac[(ar + 8) * LA + k0 + l + 4]);
            } else {
                a[0] = __float_as_uint(Ac[ar * LA + k0 + l]);
                a[1] = __float_as_uint(Ac[(ar + 8) * LA + k0 + l]);
                a[2] = __float_as_uint(Ac[ar * LA + k0 + l + 4]);
                a[3] = __float_as_uint(Ac[(ar + 8) * LA + k0 + l + 4]);
            }
#pragma unroll
            for (int j = 0; j < 4; j++) {
                unsigned b[2];
                const int bc = wn * 32 + j * 8 + g;
                if (CVT) {
                    b[0] = tf32_bits(Bc[(k0 + l) * LB + bc]);
                    b[1] = tf32_bits(Bc[(k0 + l + 4) * LB + bc]);
                } else {
                    b[0] = __float_as_uint(Bc[(k0 + l) * LB + bc]);
                    b[1] = __float_as_uint(Bc[(k0 + l + 4) * LB + bc]);
                }
                mma_tf32(c[j], a, b);
            }
        }
    }

    const int row0 = r0 + wm * 16 + g;
#pragma unroll
    for (int j = 0; j < 4; j++) {
        const int col = cb0 + wn * 32 + j * 8 + l * 2;
        const float b0 = bias[col], b1 = bias[col + 1];
        float v00 = c[j][0] + b0, v01 = c[j][1] + b1;
        float v10 = c[j][2] + b0, v11 = c[j][3] + b1;
        if (RELU_RND) {   // f1: relu then round (feeds f2's cvt-free A)
            v00 = to_tf32(fmaxf(v00, 0.f)); v01 = to_tf32(fmaxf(v01, 0.f));
            v10 = to_tf32(fmaxf(v10, 0.f)); v11 = to_tf32(fmaxf(v11, 0.f));
        }
        *(float2*)&out[(size_t)row0 * ldW + col]       = make_float2(v00, v01);
        *(float2*)&out[(size_t)(row0 + 8) * ldW + col] = make_float2(v10, v11);
    }
    gdc_launch();
}

template<bool RELU_RND>
__global__ __launch_bounds__(256) void gemm_tc(
    const float* __restrict__ in, const float* __restrict__ W,
    const float* __restrict__ bias, float* __restrict__ out,
    int KTOT, int ldW)
{
    extern __shared__ float smem[];
    gdc_wait();
    gemm_body<RELU_RND, false>(in, KTOT, W, bias, out, KTOT, ldW,
                               blockIdx.x * 64, blockIdx.y * 64, smem, smem + 3 * ASZ);
}

// fused QKV (raw operands, in-loop cvt) + piggybacked weight rounding:
// blockIdx.y in [0,12) -> GEMM; [12,14) -> round Wo/Wf1/Wf2 for later kernels.
__global__ __launch_bounds__(256) void gemm_qkv(
    const float* __restrict__ x,
    const float* __restrict__ Wq, const float* __restrict__ bq, float* __restrict__ oq,
    const float* __restrict__ Wk, const float* __restrict__ bk, float* __restrict__ ok,
    const float* __restrict__ Wv, const float* __restrict__ bv, float* __restrict__ ov,
    const float* __restrict__ Wo,  float* __restrict__ dWo,
    const float* __restrict__ Wf1, float* __restrict__ dWf1,
    const float* __restrict__ Wf2, float* __restrict__ dWf2)
{
    extern __shared__ float smem[];
    if (blockIdx.y >= 12) {
        constexpr int n1 = HIDD * HIDD / 4;
        constexpr int n2 = HIDD * FFND / 4;
        constexpr int n3 = FFND * HIDD / 4;
        const int base = ((blockIdx.y - 12) * gridDim.x + blockIdx.x) * blockDim.x + threadIdx.x;
        const int step = 2 * gridDim.x * blockDim.x;
        for (int i = base; i < n1 + n2 + n3; i += step) {
            const float4* s; float4* d; int j = i;
            if (j < n1)           { s = (const float4*)Wo;  d = (float4*)dWo; }
            else if (j < n1 + n2) { j -= n1; s = (const float4*)Wf1; d = (float4*)dWf1; }
            else                  { j -= n1 + n2; s = (const float4*)Wf2; d = (float4*)dWf2; }
            float4 v = s[j];
            d[j] = make_float4(to_tf32(v.x), to_tf32(v.y), to_tf32(v.z), to_tf32(v.w));
        }
        gdc_launch();
        return;
    }
    const int sel = blockIdx.y >> 2;
    const float* W = (sel == 0) ? Wq : (sel == 1) ? Wk : Wv;
    const float* b = (sel == 0) ? bq : (sel == 1) ? bk : bv;
    float*       o = (sel == 0) ? oq : (sel == 1) ? ok : ov;
    gemm_body<false, true>(x, HIDD, W, b, o, HIDD, HIDD,
                           blockIdx.x * 64, (blockIdx.y & 3) * 64, smem, smem + 3 * ASZ);
}

// Wo, split-K=2: grid (48, 4, 2). K=128 per split; operands pre-rounded.
__global__ __launch_bounds__(256) void gemm_wo(
    const float* __restrict__ in, const float* __restrict__ Wo,
    const float* __restrict__ zero, float* __restrict__ part)
{
    extern __shared__ float smem[];
    gdc_wait();
    const int z = blockIdx.z;
    gemm_body<false, false>(in + z * (HIDD / 2), HIDD,
                            Wo + (size_t)z * (HIDD / 2) * HIDD,
                            zero, part + (size_t)z * NN * HIDD, HIDD / 2, HIDD,
                            blockIdx.x * 64, blockIdx.y * 64, smem, smem + 3 * ASZ);
}

// FFN-down, split-K=4: grid (48, 4, 4). K=256 per split; pre-rounded.
__global__ __launch_bounds__(256) void gemm_f2(
    const float* __restrict__ ffn, const float* __restrict__ Wf2,
    const float* __restrict__ zero, float* __restrict__ part)
{
    extern __shared__ float smem[];
    gdc_wait();
    const int z = blockIdx.z;
    gemm_body<false, false>(ffn + z * (FFND / 4), FFND,
                            Wf2 + (size_t)z * (FFND / 4) * HIDD,
                            zero, part + (size_t)z * NN * HIDD, FFND / 4, HIDD,
                            blockIdx.x * 64, blockIdx.y * 64, smem, smem + 3 * ASZ);
}

// ---------------- attention: warp per (node, head), fused edge bias -------
// output rounded to tf32 (feeds Wo's cvt-free A operand)
__global__ __launch_bounds__(256) void attn2(
    const int*   __restrict__ neighbors,
    const float* __restrict__ ef,
    const float* __restrict__ We,
    const float* __restrict__ be,
    const float* __restrict__ Q,
    const float* __restrict__ K,
    const float* __restrict__ V,
    float* __restrict__ outp)
{
    const int n = blockIdx.x;
    const int h = threadIdx.x >> 5;
    const int lane = threadIdx.x & 31;
    const int tid = threadIdx.x;
    const unsigned FULL = 0xffffffffu;

    __shared__ float efs[DEG][33];
    __shared__ float Wes[256];
    __shared__ int s_nbr[DEG];
    __shared__ unsigned s_keep;

    // prologue independent of predecessor (ef/We/neighbors are inputs)
    {
        const float* eb = ef + (size_t)n * DEG * EDIM;
#pragma unroll
        for (int i = 0; i < 2; i++) {
            int lin = tid + i * 256;
            efs[lin >> 5][lin & 31] = eb[lin];
        }
        Wes[tid] = We[tid];
    }
    if (h == 0) {
        int v = (lane < DEG) ? neighbors[n * DEG + lane] : -1;
        bool keep = (lane < DEG);
#pragma unroll
        for (int d2 = 1; d2 < DEG; d2++) {
            int other = __shfl_sync(FULL, v, d2);
            if (d2 > lane && other == v) keep = false;
        }
        unsigned km = __ballot_sync(FULL, keep && lane < DEG);
        if (lane < DEG) s_nbr[lane] = v;
        if (lane == 0) s_keep = km;
    }
    __syncthreads();

    gdc_wait();   // Q/K/V produced by qkv

    const int nb_l = (lane < DEG) ? s_nbr[lane] : 0;
    const unsigned km = s_keep;
    const float q = Q[(size_t)n * HIDD + h * DH + lane];

    float bias = be[h];
    if (lane < DEG) {
#pragma unroll
        for (int k = 0; k < EDIM; k++)
            bias = fmaf(efs[lane][k], Wes[k * 8 + h], bias);
    }

    float kv[DEG];
#pragma unroll
    for (int d = 0; d < DEG; d++) {
        int s = __shfl_sync(FULL, nb_l, d);
        kv[d] = K[(size_t)s * HIDD + h * DH + lane];
    }
    float myscore = -1e30f;
#pragma unroll
    for (int d = 0; d < DEG; d++) {
        float p = q * kv[d];
#pragma unroll
        for (int o = 16; o; o >>= 1) p += __shfl_xor_sync(FULL, p, o);
        if (lane == d) myscore = p;
    }

    const bool keep = (lane < DEG) && ((km >> lane) & 1u);
    myscore = keep ? fmaf(myscore, 0.17677669529663687f, bias) : -1e30f;

    float m = myscore;
#pragma unroll
    for (int o = 16; o; o >>= 1) m = fmaxf(m, __shfl_xor_sync(FULL, m, o));
    float e = keep ? expf(myscore - m) : 0.f;
    float ssum = e;
#pragma unroll
    for (int o = 16; o; o >>= 1) ssum += __shfl_xor_sync(FULL, ssum, o);
    const float w = e / ssum;

    float vv[DEG];
#pragma unroll
    for (int d = 0; d < DEG; d++) {
        int s = __shfl_sync(FULL, nb_l, d);
        vv[d] = V[(size_t)s * HIDD + h * DH + lane];
    }
    float acc = 0.f;
#pragma unroll
    for (int d = 0; d < DEG; d++) {
        float wd = __shfl_sync(FULL, w, d);
        acc = fmaf(wd, vv[d], acc);
    }
    outp[(size_t)n * HIDD + h * DH + lane] = to_tf32(acc);
    gdc_launch();
}

// ---- N-partial reduce + bias + residual + LayerNorm (warp per row) -------
template<int NPART, bool RND>
__global__ __launch_bounds__(256) void ln_red(
    const float* __restrict__ part,
    const float* __restrict__ bias2,
    const float* __restrict__ res,
    const float* __restrict__ lg, const float* __restrict__ lb,
    float* __restrict__ out)
{
    gdc_wait();
    const int warp = threadIdx.x >> 5, lane = threadIdx.x & 31;
    const int row = blockIdx.x * 8 + warp;
    const size_t off = (size_t)row * HIDD;
    const float4* rp  = (const float4*)(res + off);
    const float4* b2p = (const float4*)bias2;

    float4 v0, v1;
    {
        float4 r = rp[lane], c = b2p[lane];
        v0 = make_float4(r.x + c.x, r.y + c.y, r.z + c.z, r.w + c.w);
    }
    {
        float4 r = rp[lane + 32], c = b2p[lane + 32];
        v1 = make_float4(r.x + c.x, r.y + c.y, r.z + c.z, r.w + c.w);
    }
#pragma unroll
    for (int i = 0; i < NPART; i++) {
        const float4* pp = (const float4*)(part + (size_t)i * NN * HIDD + off);
        float4 a = pp[lane], b = pp[lane + 32];
        v0.x += a.x; v0.y += a.y; v0.z += a.z; v0.w += a.w;
        v1.x += b.x; v1.y += b.y; v1.z += b.z; v1.w += b.w;
    }

    float s  = v0.x + v0.y + v0.z + v0.w + v1.x + v1.y + v1.z + v1.w;
    float s2 = v0.x*v0.x + v0.y*v0.y + v0.z*v0.z + v0.w*v0.w
             + v1.x*v1.x + v1.y*v1.y + v1.z*v1.z + v1.w*v1.w;
#pragma unroll
    for (int o = 16; o; o >>= 1) {
        s  += __shfl_xor_sync(0xffffffffu, s,  o);
        s2 += __shfl_xor_sync(0xffffffffu, s2, o);
    }
    const float mu = s * (1.f / 256.f);
    const float var = fmaxf(s2 * (1.f / 256.f) - mu * mu, 0.f);
    const float rs = rsqrtf(var + 1e-5f);

    const float4* gp = (const float4*)lg;
    const float4* bp = (const float4*)lb;
    float4 g0 = gp[lane], g1 = gp[lane + 32];
    float4 b0 = bp[lane], b1 = bp[lane + 32];
    float4 o0, o1;
    o0.x = (v0.x - mu) * rs * g0.x + b0.x;  o0.y = (v0.y - mu) * rs * g0.y + b0.y;
    o0.z = (v0.z - mu) * rs * g0.z + b0.z;  o0.w = (v0.w - mu) * rs * g0.w + b0.w;
    o1.x = (v1.x - mu) * rs * g1.x + b1.x;  o1.y = (v1.y - mu) * rs * g1.y + b1.y;
    o1.z = (v1.z - mu) * rs * g1.z + b1.z;  o1.w = (v1.w - mu) * rs * g1.w + b1.w;
    if (RND) {
        o0 = make_float4(to_tf32(o0.x), to_tf32(o0.y), to_tf32(o0.z), to_tf32(o0.w));
        o1 = make_float4(to_tf32(o1.x), to_tf32(o1.y), to_tf32(o1.z), to_tf32(o1.w));
    }
    ((float4*)(out + off))[lane]      = o0;
    ((float4*)(out + off))[lane + 32] = o1;
    gdc_launch();
}

// ---------------- launch ----------------
extern "C" void kernel_launch(void* const* d_in, const int* in_sizes, int n_in,
                              void* d_out, int out_size)
{
    const float* x    = (const float*)d_in[0];
    const int*   nb   = (const int*)  d_in[1];
    const float* ef   = (const float*)d_in[2];
    const float* Wq   = (const float*)d_in[3];
    const float* bq   = (const float*)d_in[4];
    const float* Wk   = (const float*)d_in[5];
    const float* bk   = (const float*)d_in[6];
    const float* Wv   = (const float*)d_in[7];
    const float* bv   = (const float*)d_in[8];
    const float* We   = (const float*)d_in[9];
    const float* be   = (const float*)d_in[10];
    const float* Wo   = (const float*)d_in[11];
    const float* bo   = (const float*)d_in[12];
    const float* ln1g = (const float*)d_in[13];
    const float* ln1b = (const float*)d_in[14];
    const float* ln2g = (const float*)d_in[15];
    const float* ln2b = (const float*)d_in[16];
    const float* Wf1  = (const float*)d_in[17];
    const float* bf1  = (const float*)d_in[18];
    const float* Wf2  = (const float*)d_in[19];
    const float* bf2  = (const float*)d_in[20];
    float* out = (float*)d_out;

    float *pQ, *pK, *pV, *pA, *pH1, *pF, *pP, *pZ;
    float *pWot, *pWf1t, *pWf2t;
    cudaGetSymbolAddress((void**)&pQ,   g_Q);
    cudaGetSymbolAddress((void**)&pK,   g_K);
    cudaGetSymbolAddress((void**)&pV,   g_V);
    cudaGetSymbolAddress((void**)&pA,   g_attn);
    cudaGetSymbolAddress((void**)&pH1,  g_h1);
    cudaGetSymbolAddress((void**)&pF,   g_ffn);
    cudaGetSymbolAddress((void**)&pP,   g_part);
    cudaGetSymbolAddress((void**)&pZ,   g_zero);
    cudaGetSymbolAddress((void**)&pWot, g_Wot);
    cudaGetSymbolAddress((void**)&pWf1t, g_Wf1t);
    cudaGetSymbolAddress((void**)&pWf2t, g_Wf2t);

    cudaFuncSetAttribute(gemm_qkv,      cudaFuncAttributeMaxDynamicSharedMemorySize, GSMEM);
    cudaFuncSetAttribute(gemm_wo,       cudaFuncAttributeMaxDynamicSharedMemorySize, GSMEM);
    cudaFuncSetAttribute(gemm_f2,       cudaFuncAttributeMaxDynamicSharedMemorySize, GSMEM);
    cudaFuncSetAttribute(gemm_tc<true>, cudaFuncAttributeMaxDynamicSharedMemorySize, GSMEM);

    // PDL launch config (programmatic stream serialization)
    cudaLaunchAttribute pa;
    pa.id = cudaLaunchAttributeProgrammaticStreamSerialization;
    pa.val.programmaticStreamSerializationAllowed = 1;
    cudaLaunchConfig_t cfg = {};
    cfg.blockDim = dim3(256, 1, 1);
    cfg.stream = 0;
    cfg.attrs = &pa;
    cfg.numAttrs = 1;

    // 1) fused QKV (in-loop cvt) + piggybacked rounding of Wo/Wf1/Wf2 (normal launch)
    gemm_qkv<<<dim3(NN / 64, 14), 256, GSMEM>>>(
        x, Wq, bq, pQ, Wk, bk, pK, Wv, bv, pV,
        Wo, pWot, Wf1, pWf1t, Wf2, pWf2t);

    // 2) sparse attention (PDL)
    cfg.gridDim = dim3(NN, 1, 1);
    cfg.dynamicSmemBytes = 0;
    cudaLaunchKernelEx(&cfg, attn2, nb, ef, We, be,
                       (const float*)pQ, (const float*)pK, (const float*)pV, pA);

    // 3) Wo split-K=2 (PDL)
    cfg.gridDim = dim3(NN / 64, HIDD / 64, 2);
    cfg.dynamicSmemBytes = GSMEM;
    cudaLaunchKernelEx(&cfg, gemm_wo, (const float*)pA, (const float*)pWot,
                       (const float*)pZ, pP);

    // 4) reduce + bo + residual(x) + LN1 -> h1 rounded (PDL)
    cfg.gridDim = dim3(NN / 8, 1, 1);
    cfg.dynamicSmemBytes = 0;
    cudaLaunchKernelEx(&cfg, ln_red<2, true>, (const float*)pP, bo, x, ln1g, ln1b, pH1);

    // 5) FFN up + ReLU (PDL)
    cfg.gridDim = dim3(NN / 64, FFND / 64, 1);
    cfg.dynamicSmemBytes = GSMEM;
    cudaLaunchKernelEx(&cfg, gemm_tc<true>, (const float*)pH1, (const float*)pWf1t,
                       bf1, pF, (int)HIDD, (int)FFND);

    // 6) FFN down split-K=4 (PDL)
    cfg.gridDim = dim3(NN / 64, HIDD / 64, 4);
    cfg.dynamicSmemBytes = GSMEM;
    cudaLaunchKernelEx(&cfg, gemm_f2, (const float*)pF, (const float*)pWf2t,
                       (const float*)pZ, pP);

    // 7) reduce + bf2 + res(h1) + LN2 -> out (PDL)
    cfg.gridDim = dim3(NN / 8, 1, 1);
    cfg.dynamicSmemBytes = 0;
    cudaLaunchKernelEx(&cfg, ln_red<4, false>, (const float*)pP, bf2,
                       (const float*)pH1, ln2g, ln2b, out);
}